// round 1
// baseline (speedup 1.0000x reference)
#include <cuda_runtime.h>
#include <math.h>

#define RES  512
#define HID  128
#define NSEG 129   // HID kinks -> HID+1 segments

// -------- persistent device-side tables (rebuilt every launch; deterministic) ----
__device__ float  g_sorted_t[HID];
__device__ float2 g_seg[NSEG * HID];   // [s*HID + permuted_j] = (w3*alpha, w3*beta)
__device__ int    g_perm[HID];
__device__ int    g_P;                 // count of j with w3[j] >= 0

// ============================================================================
// Setup kernel 1: sort kink locations t_i = -b1_i/w1_i (rank sort, 128 elems),
// and build the sign-grouping permutation for w3 (positives first).
// ============================================================================
__global__ void setup_sort(const float* __restrict__ w1,
                           const float* __restrict__ b1,
                           const float* __restrict__ w3) {
    __shared__ float ts[HID];
    __shared__ int   pf[HID];
    int i = threadIdx.x;
    float w = w1[i], b = b1[i];
    float t = -b / w;
    ts[i] = t;
    pf[i] = (w3[i] >= 0.0f) ? 1 : 0;
    __syncthreads();

    int rank = 0;
    for (int j = 0; j < HID; j++) {
        float tj = ts[j];
        rank += (tj < t) || (tj == t && j < i);   // deterministic tie-break
    }
    g_sorted_t[rank] = t;

    int P = 0;
    for (int j = 0; j < HID; j++) P += pf[j];
    int c;
    if (pf[i]) {
        c = 0;
        for (int j = 0; j < i; j++) c += pf[j];
    } else {
        c = P;
        for (int j = 0; j < i; j++) c += (1 - pf[j]);
    }
    g_perm[i] = c;
    if (i == 0) g_P = P;
}

// ============================================================================
// Setup kernel 2: per segment s, evaluate the active set at the segment
// midpoint and build affine coefficients of layer-2 pre-activation:
//   z_j(F) = alpha_j*F + beta_j  (beta includes b2_j)
// Store (w3_j*alpha, w3_j*beta) at the sign-permuted slot.
// ============================================================================
__global__ void setup_table(const float* __restrict__ w1,
                            const float* __restrict__ b1,
                            const float* __restrict__ w2,
                            const float* __restrict__ b2,
                            const float* __restrict__ w3) {
    int s = blockIdx.x;        // 0..128
    int j = threadIdx.x;       // 0..127
    __shared__ float smid;
    if (j == 0) {
        float Fm;
        if (s == 0)           Fm = g_sorted_t[0]       - 1.0f;
        else if (s == NSEG-1) Fm = g_sorted_t[HID - 1] + 1.0f;
        else                  Fm = 0.5f * (g_sorted_t[s-1] + g_sorted_t[s]);
        smid = Fm;
    }
    __syncthreads();
    float Fm = smid;

    float alpha = 0.0f, beta = 0.0f;
    for (int i = 0; i < HID; i++) {
        float wi = w1[i], bi = b1[i];
        if (wi * Fm + bi > 0.0f) {           // neuron i active on this segment
            float w2ij = w2[i * HID + j];
            alpha = fmaf(wi, w2ij, alpha);
            beta  = fmaf(bi, w2ij, beta);
        }
    }
    beta += b2[j];
    float w3j = w3[j];
    g_seg[s * HID + g_perm[j]] = make_float2(w3j * alpha, w3j * beta);
}

// ============================================================================
// Main kernel: per point, bilinear interp on 3 planes -> F, binary-search the
// segment, then out = tanh( sum_{j<P} max(g*F+d,0) + sum_{j>=P} min(g*F+d,0) + b3 ).
// Segment table lives in SMEM with layout [j*NSEG + s] (odd stride 129 ->
// mild bank conflicts for the per-lane segment gather).
// ============================================================================
__device__ __forceinline__ float interp2d(const float* __restrict__ pl,
                                          float c1, float c2) {
    float c1f = floorf(c1), c2f = floorf(c2);
    int i1 = (int)c1f, i2 = (int)c2f;
    int i1c = min(i1 + 1, RES - 1);
    int i2c = min(i2 + 1, RES - 1);
    float bl = pl[i1  * RES + i2 ];
    float br = pl[i1c * RES + i2 ];
    float tl = pl[i1  * RES + i2c];
    float tr = pl[i1c * RES + i2c];
    float h = c1 - c1f, v = c2 - c2f;
    float top    = tl + (tr - tl) * h;
    float bottom = bl + (br - bl) * h;
    return bottom + (top - bottom) * v;
}

__global__ __launch_bounds__(1024, 1)
void neusdf_main(const float* __restrict__ points,
                 const float* __restrict__ xy,
                 const float* __restrict__ yz,
                 const float* __restrict__ xz,
                 const float* __restrict__ b3ptr,
                 float* __restrict__ out, int N) {
    extern __shared__ float sm[];
    float2* sGD = (float2*)sm;                    // [HID][NSEG]
    float*  sT  = sm + 2 * HID * NSEG;            // [HID]
    __shared__ int   sP;
    __shared__ float sB3;

    int tid = threadIdx.x;
    // load table with [s][j] -> [j][s] relayout (coalesced global reads)
    for (int idx = tid; idx < NSEG * HID; idx += blockDim.x) {
        int s = idx >> 7;        // idx / HID
        int j = idx & (HID - 1); // idx % HID
        sGD[j * NSEG + s] = g_seg[idx];
    }
    if (tid < HID) sT[tid] = g_sorted_t[tid];
    if (tid == 0) { sP = g_P; sB3 = b3ptr[0]; }
    __syncthreads();

    int   P  = sP;
    float b3 = sB3;
    int stride = gridDim.x * blockDim.x;

    for (int i = blockIdx.x * blockDim.x + tid; i < N; i += stride) {
        float px = points[3 * i + 0];
        float py = points[3 * i + 1];
        float pz = points[3 * i + 2];
        float x = (px + 1.0f) * 0.5f * (float)(RES - 1);
        float y = (py + 1.0f) * 0.5f * (float)(RES - 1);
        float z = (pz + 1.0f) * 0.5f * (float)(RES - 1);

        float F = interp2d(xy, x, y) + interp2d(xz, x, z) + interp2d(yz, y, z);

        // segment index: count of sorted kinks <= F  (branchless binary search)
        int s = 0;
        #pragma unroll
        for (int b = 128; b > 0; b >>= 1) {
            int k = s + b - 1;
            if (k < HID && sT[k] <= F) s += b;
        }

        float accP = 0.0f, accM = 0.0f;
        int j = 0;
        #pragma unroll 4
        for (; j < P; j++) {                      // w3_j >= 0 group
            float2 gd = sGD[j * NSEG + s];
            accP += fmaxf(fmaf(gd.x, F, gd.y), 0.0f);
        }
        #pragma unroll 4
        for (; j < HID; j++) {                    // w3_j < 0 group
            float2 gd = sGD[j * NSEG + s];
            accM += fminf(fmaf(gd.x, F, gd.y), 0.0f);
        }
        out[i] = tanhf(accP + accM + b3);
    }
}

// ============================================================================
extern "C" void kernel_launch(void* const* d_in, const int* in_sizes, int n_in,
                              void* d_out, int out_size) {
    const float* points = (const float*)d_in[0];
    const float* xy     = (const float*)d_in[1];
    const float* yz     = (const float*)d_in[2];
    const float* xz     = (const float*)d_in[3];
    const float* w1     = (const float*)d_in[4];
    const float* b1     = (const float*)d_in[5];
    const float* w2     = (const float*)d_in[6];
    const float* b2     = (const float*)d_in[7];
    const float* w3     = (const float*)d_in[8];
    const float* b3     = (const float*)d_in[9];
    int N = in_sizes[0] / 3;

    setup_sort<<<1, HID>>>(w1, b1, w3);
    setup_table<<<NSEG, HID>>>(w1, b1, w2, b2, w3);

    size_t smem = sizeof(float2) * NSEG * HID + sizeof(float) * HID;
    cudaFuncSetAttribute(neusdf_main,
                         cudaFuncAttributeMaxDynamicSharedMemorySize,
                         (int)smem);
    neusdf_main<<<152, 1024, smem>>>(points, xy, yz, xz, b3,
                                     (float*)d_out, N);
}

// round 2
// speedup vs baseline: 1.1760x; 1.1760x over previous
#include <cuda_runtime.h>
#include <math.h>
#include <float.h>

#define RES   512
#define HID   128
#define NSEG  (HID + 1)            // 129 outer segments
#define KMAX  (NSEG + HID * NSEG)  // 16641 worst-case final segments
#define KPAD  16642                // even pad so float2 region is 8B aligned

// ---------------- persistent device tables (rebuilt every launch) ----------
__device__ float  g_sorted_t[HID];          // sorted outer kinks
__device__ float2 g_ab[NSEG * HID];         // per (outer seg, j): (alpha, beta)
__device__ float  g_kinks[NSEG * HID];      // per outer seg: sorted inner kinks
__device__ int    g_m[NSEG];                // # inner kinks per outer seg
__device__ float  g_flatT[KMAX];            // global sorted segment starts
__device__ float2 g_flatAB[KMAX];           // per final segment: (A, B+b3)
__device__ int    g_K;                      // actual number of final segments

// ============================================================================
// Setup 1: per outer segment s (129 blocks x 128 threads):
//  - sort outer kinks t_i = -b1_i/w1_i (rank sort, replicated per block)
//  - compute alpha_j, beta_j = affine coeffs of layer-2 preact on segment s
//  - find inner kinks u_j = -beta_j/alpha_j lying strictly inside the segment,
//    rank-sort them, store sorted + count
// ============================================================================
__global__ void setup_seg(const float* __restrict__ w1,
                          const float* __restrict__ b1,
                          const float* __restrict__ w2,
                          const float* __restrict__ b2) {
    __shared__ float sw1[HID], sb1[HID], st[HID], ssort[HID], su[HID];
    __shared__ int   sval[HID];
    int j = threadIdx.x;
    int s = blockIdx.x;

    float w = w1[j], b = b1[j];
    sw1[j] = w; sb1[j] = b;
    float t = -b / w;
    st[j] = t;
    __syncthreads();

    int rank = 0;
    for (int k = 0; k < HID; k++) {
        float tk = st[k];
        rank += (tk < t) || (tk == t && k < j);
    }
    ssort[rank] = t;
    __syncthreads();
    if (s == 0) g_sorted_t[j] = ssort[j];

    float lo = (s == 0)   ? -FLT_MAX : ssort[s - 1];
    float hi = (s == HID) ?  FLT_MAX : ssort[s];
    float Fm = (s == 0)   ? ssort[0] - 1.0f
             : (s == HID) ? ssort[HID - 1] + 1.0f
                          : 0.5f * (lo + hi);

    float alpha = 0.0f, beta = 0.0f;
    for (int i = 0; i < HID; i++) {
        if (fmaf(sw1[i], Fm, sb1[i]) > 0.0f) {
            float w2ij = w2[i * HID + j];
            alpha = fmaf(sw1[i], w2ij, alpha);
            beta  = fmaf(sb1[i], w2ij, beta);
        }
    }
    beta += b2[j];
    g_ab[s * HID + j] = make_float2(alpha, beta);

    float u = -beta / alpha;
    bool valid = (alpha != 0.0f) && (u > lo) && (u < hi);  // NaN -> false
    su[j] = valid ? u : FLT_MAX;
    sval[j] = valid ? 1 : 0;
    __syncthreads();

    int m = 0, r = 0;
    float uj = su[j];
    for (int k = 0; k < HID; k++) {
        m += sval[k];
        float uk = su[k];
        r += (uk < uj) || (uk == uj && k < j);
    }
    if (valid) g_kinks[s * HID + r] = u;
    if (j == 0) g_m[s] = m;
}

// ============================================================================
// Setup 2: per outer segment s (129 blocks x 256 threads = 8 warps):
// build the flat global table. Sub-interval r of segment s gets
//   A = sum_{j active} w3_j*alpha_j,  B = sum_{j active} w3_j*beta_j + b3,
// active decided at the sub-interval midpoint (exactly matching relu signs).
// Flat concatenation (segments in order, kinks sorted inside) is globally
// sorted by construction.
// ============================================================================
__global__ void setup_final(const float* __restrict__ w3,
                            const float* __restrict__ b3) {
    int s = blockIdx.x;
    __shared__ int   soff, snsub;
    __shared__ float slo, shi;
    if (threadIdx.x == 0) {
        int off = s;
        for (int k = 0; k < s; k++) off += g_m[k];
        soff  = off;
        snsub = g_m[s] + 1;
        slo = (s == 0)   ? -FLT_MAX : g_sorted_t[s - 1];
        shi = (s == HID) ?  FLT_MAX : g_sorted_t[s];
    }
    __syncthreads();
    int   off = soff, nsub = snsub;
    float segLo = slo, segHi = shi;
    float b3v = b3[0];
    int wid = threadIdx.x >> 5, lane = threadIdx.x & 31;

    for (int r = wid; r < nsub; r += 8) {
        float lo_r = (r == 0)        ? segLo : g_kinks[s * HID + r - 1];
        float hi_r = (r == nsub - 1) ? segHi : g_kinks[s * HID + r];
        float Fm;
        if (lo_r == -FLT_MAX)      Fm = hi_r - 1.0f;
        else if (hi_r == FLT_MAX)  Fm = lo_r + 1.0f;
        else                       Fm = 0.5f * (lo_r + hi_r);

        float A = 0.0f, B = 0.0f;
        for (int q = lane; q < HID; q += 32) {
            float2 ab = g_ab[s * HID + q];
            if (fmaf(ab.x, Fm, ab.y) > 0.0f) {
                float w3q = w3[q];
                A = fmaf(w3q, ab.x, A);
                B = fmaf(w3q, ab.y, B);
            }
        }
        #pragma unroll
        for (int d = 16; d; d >>= 1) {
            A += __shfl_xor_sync(0xffffffffu, A, d);
            B += __shfl_xor_sync(0xffffffffu, B, d);
        }
        if (lane == 0) {
            g_flatT[off + r]  = lo_r;
            g_flatAB[off + r] = make_float2(A, B + b3v);
        }
    }
    if (s == HID && threadIdx.x == 0) g_K = soff + nsub;
}

// ============================================================================
// Main kernel: triplane bilinear interp -> F, 15-step binary-lift over the
// flat SMEM breakpoint table, out = tanh(A*F + B).
// ============================================================================
__device__ __forceinline__ float interp2d(const float* __restrict__ pl,
                                          float c1, float c2) {
    float c1f = floorf(c1), c2f = floorf(c2);
    int i1 = (int)c1f, i2 = (int)c2f;
    int i1c = min(i1 + 1, RES - 1);
    int i2c = min(i2 + 1, RES - 1);
    float bl = pl[i1  * RES + i2 ];
    float br = pl[i1c * RES + i2 ];
    float tl = pl[i1  * RES + i2c];
    float tr = pl[i1c * RES + i2c];
    float h = c1 - c1f, v = c2 - c2f;
    float top    = tl + (tr - tl) * h;
    float bottom = bl + (br - bl) * h;
    return bottom + (top - bottom) * v;
}

__global__ __launch_bounds__(1024, 1)
void neusdf_main(const float* __restrict__ points,
                 const float* __restrict__ xy,
                 const float* __restrict__ yz,
                 const float* __restrict__ xz,
                 float* __restrict__ out, int N) {
    extern __shared__ float sm[];
    float*  sT  = sm;                        // [K] segment starts
    float2* sAB = (float2*)(sm + KPAD);      // [K] (A,B)
    __shared__ int sKsh;
    if (threadIdx.x == 0) sKsh = g_K;
    __syncthreads();
    int K = sKsh;

    for (int idx = threadIdx.x; idx < K; idx += blockDim.x) {
        sT[idx]  = g_flatT[idx];
        sAB[idx] = g_flatAB[idx];
    }
    __syncthreads();

    int stride = gridDim.x * blockDim.x;
    for (int i = blockIdx.x * blockDim.x + threadIdx.x; i < N; i += stride) {
        float px = points[3 * i + 0];
        float py = points[3 * i + 1];
        float pz = points[3 * i + 2];
        float x = (px + 1.0f) * 0.5f * (float)(RES - 1);
        float y = (py + 1.0f) * 0.5f * (float)(RES - 1);
        float z = (pz + 1.0f) * 0.5f * (float)(RES - 1);

        float F = interp2d(xy, x, y) + interp2d(xz, x, z) + interp2d(yz, y, z);

        // largest k with sT[k] <= F (sT[0] = -FLT_MAX)
        int s = 0;
        #pragma unroll
        for (int b = 16384; b; b >>= 1) {
            int k = s + b;
            if (k < K && sT[k] <= F) s = k;
        }
        float2 ab = sAB[s];
        out[i] = tanhf(fmaf(ab.x, F, ab.y));
    }
}

// ============================================================================
extern "C" void kernel_launch(void* const* d_in, const int* in_sizes, int n_in,
                              void* d_out, int out_size) {
    const float* points = (const float*)d_in[0];
    const float* xy     = (const float*)d_in[1];
    const float* yz     = (const float*)d_in[2];
    const float* xz     = (const float*)d_in[3];
    const float* w1     = (const float*)d_in[4];
    const float* b1     = (const float*)d_in[5];
    const float* w2     = (const float*)d_in[6];
    const float* b2     = (const float*)d_in[7];
    const float* w3     = (const float*)d_in[8];
    const float* b3     = (const float*)d_in[9];
    int N = in_sizes[0] / 3;

    setup_seg<<<NSEG, HID>>>(w1, b1, w2, b2);
    setup_final<<<NSEG, 256>>>(w3, b3);

    size_t smem = sizeof(float) * KPAD + sizeof(float2) * KMAX;  // ~195 KB
    static int smem_set = 0;
    cudaFuncSetAttribute(neusdf_main,
                         cudaFuncAttributeMaxDynamicSharedMemorySize,
                         (int)smem);
    (void)smem_set;

    int nsm = 148;
    cudaDeviceGetAttribute(&nsm, cudaDevAttrMultiProcessorCount, 0);

    neusdf_main<<<nsm, 1024, smem>>>(points, xy, yz, xz, (float*)d_out, N);
}